// round 14
// baseline (speedup 1.0000x reference)
#include <cuda_runtime.h>
#include <cuda_fp16.h>
#include <cuda_bf16.h>
#include <stdint.h>

#define BSZ   8
#define LEN   2048
#define HIDN  1024
#define NHD   16
#define HDIM  64
#define M_TOT (BSZ * LEN)
#define FIX_TAU 4e-3f
#define FIX_CAP (M_TOT * NHD)

__device__ __half g_V1[(size_t)M_TOT * (NHD * HDIM)];
__device__ __half g_Xh[(size_t)M_TOT * HIDN];
__device__ __half g_WTh[(size_t)2048 * HIDN];   // [n][k] fp16 transposed weights
__device__ float  g_KTf[(size_t)1024 * HIDN];   // [n][k] fp32 transposed K weights
__device__ float  g_dots[M_TOT * NHD];
__device__ int2   g_fmap[M_TOT * NHD];
__device__ int2   g_bmap[M_TOT * NHD];
__device__ int    g_fix_cnt;
__device__ int    g_fix_ids[FIX_CAP];

// ---------------- helpers ----------------
__device__ __forceinline__ uint32_t smem_u32(const void* p) {
    return (uint32_t)__cvta_generic_to_shared(p);
}
__device__ __forceinline__ void cp_async16(uint32_t saddr, const void* gptr) {
    asm volatile("cp.async.ca.shared.global [%0], [%1], 16;\n" :: "r"(saddr), "l"(gptr));
}
__device__ __forceinline__ void cp_commit() { asm volatile("cp.async.commit_group;\n"); }
__device__ __forceinline__ void cp_wait1() { asm volatile("cp.async.wait_group 1;\n"); }

__device__ __forceinline__ void ldsm4(uint32_t* r, uint32_t addr) {
    asm volatile("ldmatrix.sync.aligned.m8n8.x4.shared.b16 {%0,%1,%2,%3}, [%4];"
        : "=r"(r[0]), "=r"(r[1]), "=r"(r[2]), "=r"(r[3]) : "r"(addr));
}
__device__ __forceinline__ void mma_f16(float* d, const uint32_t* a, const uint32_t* b) {
    asm volatile("mma.sync.aligned.m16n8k16.row.col.f32.f16.f16.f32 "
        "{%0,%1,%2,%3},{%4,%5,%6,%7},{%8,%9},{%0,%1,%2,%3};\n"
        : "+f"(d[0]), "+f"(d[1]), "+f"(d[2]), "+f"(d[3])
        : "r"(a[0]), "r"(a[1]), "r"(a[2]), "r"(a[3]), "r"(b[0]), "r"(b[1]));
}
// Neumaier compensated accumulate (branchless)
__device__ __forceinline__ void acc2(float& s, float& c, float v) {
    float t = s + v;
    float e1 = (s - t) + v;
    float e2 = (v - t) + s;
    c += (fabsf(s) >= fabsf(v)) ? e1 : e2;
    s = t;
}

// ---------------- pre-pass: X -> fp16 (+ counter init) ----------------
__global__ __launch_bounds__(256) void conv_x(const float* __restrict__ X)
{
    if (blockIdx.x == 0 && threadIdx.x == 0) g_fix_cnt = 0;
    size_t i = ((size_t)blockIdx.x * 256 + threadIdx.x) * 8;
    float4 v0 = *(const float4*)(X + i);
    float4 v1 = *(const float4*)(X + i + 4);
    __half2 h0 = __floats2half2_rn(v0.x, v0.y);
    __half2 h1 = __floats2half2_rn(v0.z, v0.w);
    __half2 h2 = __floats2half2_rn(v1.x, v1.y);
    __half2 h3 = __floats2half2_rn(v1.z, v1.w);
    uint4 o;
    o.x = *(uint32_t*)&h0; o.y = *(uint32_t*)&h1;
    o.z = *(uint32_t*)&h2; o.w = *(uint32_t*)&h3;
    *(uint4*)(g_Xh + i) = o;
}

// ---------------- pre-pass: W transpose -> fp16 [n][k] (+ fp32 for K half) ----
__global__ __launch_bounds__(256) void transpose_w(
    const float* __restrict__ Kw, const float* __restrict__ Vw)
{
    __shared__ float t[32][33];
    const int n0 = blockIdx.x * 32, k0 = blockIdx.y * 32;
    const float* W = (n0 < 1024) ? Kw : Vw;
    const int nb = n0 & 1023;
    const int tx = threadIdx.x, ty = threadIdx.y;
    #pragma unroll
    for (int r = ty; r < 32; r += 8)
        t[r][tx] = W[(size_t)(k0 + r) * 1024 + nb + tx];
    __syncthreads();
    #pragma unroll
    for (int r = ty; r < 32; r += 8) {
        float v = t[tx][r];
        g_WTh[(size_t)(n0 + r) * 1024 + k0 + tx] = __float2half_rn(v);
        if (n0 < 1024)
            g_KTf[(size_t)(n0 + r) * 1024 + k0 + tx] = v;
    }
}

// ---------------- fp16 mma GEMM: CTA 128x256x32, warp 64x64, 8 warps --------
#define AROW 80
#define TILE_A (128 * AROW)            // 10240
#define TILE_BB (256 * AROW)           // 20480
#define STAGE_B (TILE_A + TILE_BB)     // 30720
#define STG 3
#define GEMM_SMEM (STG * STAGE_B)      // 92160

__device__ __forceinline__ void load_tiles_f16(int m0, int n0, int kt, int st, uint32_t sb, int tid)
{
    const int kk = kt * 32;
    const uint32_t sA = sb + st * STAGE_B;
    const uint32_t sB = sA + TILE_A;
    #pragma unroll
    for (int i = 0; i < 2; i++) {       // A: 512 chunks
        int c = tid + i * 256, row = c >> 2, q = c & 3;
        cp_async16(sA + (uint32_t)(row * AROW + q * 16),
                   g_Xh + (size_t)(m0 + row) * 1024 + kk + q * 8);
    }
    #pragma unroll
    for (int i = 0; i < 4; i++) {       // B: 1024 chunks (256 rows)
        int c = tid + i * 256, row = c >> 2, q = c & 3;
        cp_async16(sB + (uint32_t)(row * AROW + q * 16),
                   g_WTh + (size_t)(n0 + row) * 1024 + kk + q * 8);
    }
}

__global__ __launch_bounds__(256) void gemm_f16(
    const float* __restrict__ Kb, const float* __restrict__ Vb,
    const float* __restrict__ RH)
{
    extern __shared__ char smem[];
    const uint32_t sb = smem_u32(smem);
    const int tid = threadIdx.x, wid = tid >> 5, lane = tid & 31;
    const int wm2 = wid & 1, wn2 = wid >> 1;   // 2 warps in M, 4 in N
    const int m0 = blockIdx.y * 128;
    const int j0 = blockIdx.x * 256;
    const int n0 = j0;

    float acc[4][8][4];
    #pragma unroll
    for (int a = 0; a < 4; a++)
        #pragma unroll
        for (int b = 0; b < 8; b++)
            #pragma unroll
            for (int c = 0; c < 4; c++) acc[a][b][c] = 0.f;

    load_tiles_f16(m0, n0, 0, 0, sb, tid); cp_commit();
    load_tiles_f16(m0, n0, 1, 1, sb, tid); cp_commit();

    const int j = lane >> 3, r = lane & 7;
    const int KT = 32;
    for (int kt = 0; kt < KT; kt++) {
        cp_wait1();
        __syncthreads();
        if (kt + 2 < KT) load_tiles_f16(m0, n0, kt + 2, (kt + 2) % STG, sb, tid);
        cp_commit();

        const int st = kt % STG;
        const uint32_t sA = sb + st * STAGE_B;
        const uint32_t sB = sA + TILE_A;
        #pragma unroll
        for (int kh = 0; kh < 2; kh++) {
            uint32_t af[4][4];
            const uint32_t acol = (uint32_t)((kh << 4) + ((j >> 1) << 3));
            #pragma unroll
            for (int mt = 0; mt < 4; mt++) {
                const uint32_t arow = (uint32_t)(wm2 * 64 + mt * 16 + ((j & 1) << 3) + r);
                ldsm4(af[mt], sA + arow * AROW + acol * 2);
            }
            #pragma unroll
            for (int g2 = 0; g2 < 4; g2++) {
                uint32_t bm[4];
                const uint32_t brow = (uint32_t)(wn2 * 64 + (g2 << 4) + ((j >> 1) << 3) + r);
                const uint32_t bcol = (uint32_t)((kh << 4) + ((j & 1) << 3));
                ldsm4(bm, sB + brow * AROW + bcol * 2);
                #pragma unroll
                for (int mt = 0; mt < 4; mt++) {
                    mma_f16(acc[mt][2 * g2],     af[mt], &bm[0]);
                    mma_f16(acc[mt][2 * g2 + 1], af[mt], &bm[2]);
                }
            }
        }
    }

    const int g = lane >> 2, tg = lane & 3;
    if (j0 < 1024) {
        const int head = (j0 >> 6) + wn2;   // each warp = one head (64 cols)
        const float* rh = RH + head * HDIM;
        float dotp[8];
        #pragma unroll
        for (int i = 0; i < 8; i++) dotp[i] = 0.f;
        #pragma unroll
        for (int mt = 0; mt < 4; mt++) {
            #pragma unroll
            for (int nt = 0; nt < 8; nt++) {
                int ch = nt * 8 + 2 * tg;
                int jc = j0 + wn2 * 64 + ch;
                float b0 = Kb[jc], b1 = Kb[jc + 1];
                float w0 = rh[ch], w1 = rh[ch + 1];
                float v;
                v = fmaxf(acc[mt][nt][0] + b0, 0.f); dotp[mt * 2 + 0] += v * w0;
                v = fmaxf(acc[mt][nt][1] + b1, 0.f); dotp[mt * 2 + 0] += v * w1;
                v = fmaxf(acc[mt][nt][2] + b0, 0.f); dotp[mt * 2 + 1] += v * w0;
                v = fmaxf(acc[mt][nt][3] + b1, 0.f); dotp[mt * 2 + 1] += v * w1;
            }
        }
        #pragma unroll
        for (int i = 0; i < 8; i++) {
            dotp[i] += __shfl_xor_sync(0xffffffffu, dotp[i], 1);
            dotp[i] += __shfl_xor_sync(0xffffffffu, dotp[i], 2);
        }
        if (tg == 0) {
            #pragma unroll
            for (int mt = 0; mt < 4; mt++) {
                int rr = m0 + wm2 * 64 + mt * 16 + g;
                float d0 = dotp[mt * 2 + 0], d1 = dotp[mt * 2 + 1];
                int id0 = rr * NHD + head, id1 = (rr + 8) * NHD + head;
                g_dots[id0] = d0;
                g_dots[id1] = d1;
                if (fabsf(d0 - 0.5f) < FIX_TAU) g_fix_ids[atomicAdd(&g_fix_cnt, 1)] = id0;
                if (fabsf(d1 - 0.5f) < FIX_TAU) g_fix_ids[atomicAdd(&g_fix_cnt, 1)] = id1;
            }
        }
    } else {
        #pragma unroll
        for (int mt = 0; mt < 4; mt++) {
            #pragma unroll
            for (int nt = 0; nt < 8; nt++) {
                int jv = (j0 - 1024) + wn2 * 64 + nt * 8 + 2 * tg;
                float b0 = Vb[jv], b1 = Vb[jv + 1];
                int rr = m0 + wm2 * 64 + mt * 16 + g;
                __half2 h0 = __floats2half2_rn(fmaxf(acc[mt][nt][0] + b0, 0.f),
                                               fmaxf(acc[mt][nt][1] + b1, 0.f));
                __half2 h1 = __floats2half2_rn(fmaxf(acc[mt][nt][2] + b0, 0.f),
                                               fmaxf(acc[mt][nt][3] + b1, 0.f));
                *(__half2*)&g_V1[(size_t)rr * 1024 + jv] = h0;
                *(__half2*)&g_V1[(size_t)(rr + 8) * 1024 + jv] = h1;
            }
        }
    }
}

// ---------------- compensated-fp32 fixup of near-threshold dots -------------
__global__ __launch_bounds__(256) void fixup2(
    const float* __restrict__ X, const float* __restrict__ Kb,
    const float* __restrict__ RH)
{
    __shared__ float s_s[8], s_c[8];
    const int tid = threadIdx.x, wid = tid >> 5, lane = tid & 31;
    int cnt = g_fix_cnt;
    if (cnt > FIX_CAP) cnt = FIX_CAP;

    for (int i = blockIdx.x; i < cnt; i += gridDim.x) {
        const int t = g_fix_ids[i];
        const int m = t >> 4, n = t & 15;
        const float* xr = X + ((size_t)m << 10);

        float ws = 0.f, wc = 0.f;
        #pragma unroll
        for (int hs = 0; hs < 8; hs++) {
            const int h = wid * 8 + hs;
            const float* wrow = g_KTf + ((size_t)(n * 64 + h) << 10);
            float s = 0.f, c = 0.f;
            #pragma unroll 4
            for (int it = 0; it < 32; it++) {
                int k = it * 32 + lane;
                float a = xr[k], w = wrow[k];
                float p = a * w;
                float e = fmaf(a, w, -p);
                acc2(s, c, p);
                c += e;
            }
            #pragma unroll
            for (int off = 16; off > 0; off >>= 1) {
                float s2 = __shfl_down_sync(0xffffffffu, s, off);
                float c2 = __shfl_down_sync(0xffffffffu, c, off);
                acc2(s, c, s2);
                c += c2;
            }
            if (lane == 0) {
                float pre = s + c + Kb[n * 64 + h];
                float rv = fmaxf(pre, 0.f) * RH[n * 64 + h];
                acc2(ws, wc, rv);
            }
        }
        if (lane == 0) { s_s[wid] = ws; s_c[wid] = wc; }
        __syncthreads();
        if (tid == 0) {
            float s = 0.f, c = 0.f;
            #pragma unroll
            for (int w2 = 0; w2 < 8; w2++) { acc2(s, c, s_s[w2]); c += s_c[w2]; }
            g_dots[t] = s + c;
        }
        __syncthreads();
    }
}

// ---------------- warp-segmented nearest-valid scan ----------------
struct Seg { int cnt, v1, v2; };

__device__ __forceinline__ Seg seg_combine(const Seg& prev, const Seg& cur) {
    Seg r;
    if (cur.cnt >= 2) r = cur;
    else if (cur.cnt == 1) { r.cnt = min(prev.cnt + 1, 2); r.v1 = cur.v1; r.v2 = prev.v1; }
    else r = prev;
    return r;
}

__global__ void scan_kernel()
{
    const int bidx = blockIdx.x >> 4;
    const int n = blockIdx.x & 15;
    const int lane = threadIdx.x;
    const int base_l = lane * 64;

    const float* dp = g_dots + ((size_t)bidx * LEN) * NHD + n;
    unsigned long long bits = 0ull;
    for (int j = 0; j < 64; j++)
        if (__ldg(&dp[(size_t)(base_l + j) * NHD]) > 0.5f) bits |= (1ull << j);

    { // forward: ignore pos 0, defaults 0
        unsigned long long fb = bits;
        if (lane == 0) fb &= ~1ull;
        Seg s; s.cnt = 0; s.v1 = 0; s.v2 = 0;
        for (int j = 0; j < 64; j++)
            if ((fb >> j) & 1ull) { s.v2 = s.v1; s.v1 = base_l + j; s.cnt = min(s.cnt + 1, 2); }
        Seg inc = s;
        for (int d = 1; d < 32; d <<= 1) {
            Seg o;
            o.cnt = __shfl_up_sync(0xffffffffu, inc.cnt, d);
            o.v1  = __shfl_up_sync(0xffffffffu, inc.v1, d);
            o.v2  = __shfl_up_sync(0xffffffffu, inc.v2, d);
            if (lane >= d) inc = seg_combine(o, inc);
        }
        Seg ex;
        ex.cnt = __shfl_up_sync(0xffffffffu, inc.cnt, 1);
        ex.v1  = __shfl_up_sync(0xffffffffu, inc.v1, 1);
        ex.v2  = __shfl_up_sync(0xffffffffu, inc.v2, 1);
        if (lane == 0) { ex.cnt = 0; ex.v1 = 0; ex.v2 = 0; }
        int a = (ex.cnt >= 1) ? ex.v1 : 0;
        int b = (ex.cnt >= 2) ? ex.v2 : 0;
        int2* out = g_fmap + ((size_t)bidx * LEN) * NHD + n;
        for (int j = 0; j < 64; j++) {
            int p = base_l + j;
            if ((fb >> j) & 1ull) { b = a; a = p; }
            out[(size_t)p * NHD] = make_int2(a, b);
        }
    }

    { // backward: ignore pos L-1, store mirrored index, defaults L-1
        unsigned long long bb = bits;
        if (lane == 31) bb &= ~(1ull << 63);
        Seg s; s.cnt = 0; s.v1 = LEN - 1; s.v2 = LEN - 1;
        for (int j = 63; j >= 0; j--)
            if ((bb >> j) & 1ull) { s.v2 = s.v1; s.v1 = (LEN - 1) - (base_l + j); s.cnt = min(s.cnt + 1, 2); }
        Seg inc = s;
        for (int d = 1; d < 32; d <<= 1) {
            Seg o;
            o.cnt = __shfl_down_sync(0xffffffffu, inc.cnt, d);
            o.v1  = __shfl_down_sync(0xffffffffu, inc.v1, d);
            o.v2  = __shfl_down_sync(0xffffffffu, inc.v2, d);
            if (lane + d < 32) inc = seg_combine(o, inc);
        }
        Seg ex;
        ex.cnt = __shfl_down_sync(0xffffffffu, inc.cnt, 1);
        ex.v1  = __shfl_down_sync(0xffffffffu, inc.v1, 1);
        ex.v2  = __shfl_down_sync(0xffffffffu, inc.v2, 1);
        if (lane == 31) { ex.cnt = 0; ex.v1 = LEN - 1; ex.v2 = LEN - 1; }
        int a = (ex.cnt >= 1) ? ex.v1 : (LEN - 1);
        int b = (ex.cnt >= 2) ? ex.v2 : (LEN - 1);
        int2* out = g_bmap + ((size_t)bidx * LEN) * NHD + n;
        for (int j = 63; j >= 0; j--) {
            int p = base_l + j;
            if ((bb >> j) & 1ull) { b = a; a = (LEN - 1) - p; }
            out[(size_t)p * NHD] = make_int2(a, b);
        }
    }
}

// ---------------- weighted gather (fp16 V1) ----------------
__global__ __launch_bounds__(256) void gather_kernel(
    const float* __restrict__ Bw, float* __restrict__ out)
{
    int gid = blockIdx.x * 16 + (threadIdx.x >> 4);
    int q = threadIdx.x & 15;
    int n = gid & 15;
    int bl = gid >> 4;
    int b = bl >> 11;
    int2 fm = g_fmap[(size_t)bl * NHD + n];
    int2 bm = g_bmap[(size_t)bl * NHD + n];
    const __half* vbase = g_V1 + (((size_t)b << 11) << 10);
    size_t coff = (size_t)n * 64 + q * 4;
    uint2 u0 = *(const uint2*)(vbase + ((size_t)fm.x << 10) + coff);
    uint2 u1 = *(const uint2*)(vbase + ((size_t)fm.y << 10) + coff);
    uint2 u2 = *(const uint2*)(vbase + ((size_t)bm.x << 10) + coff);
    uint2 u3 = *(const uint2*)(vbase + ((size_t)bm.y << 10) + coff);
    float w0 = Bw[n * 4 + 0], w1 = Bw[n * 4 + 1], w2 = Bw[n * 4 + 2], w3 = Bw[n * 4 + 3];
    float2 a0 = __half22float2(*(__half2*)&u0.x), a1 = __half22float2(*(__half2*)&u0.y);
    float2 b0 = __half22float2(*(__half2*)&u1.x), b1 = __half22float2(*(__half2*)&u1.y);
    float2 c0 = __half22float2(*(__half2*)&u2.x), c1 = __half22float2(*(__half2*)&u2.y);
    float2 d0 = __half22float2(*(__half2*)&u3.x), d1 = __half22float2(*(__half2*)&u3.y);
    float4 r;
    r.x = w0 * a0.x + w1 * b0.x + w2 * c0.x + w3 * d0.x;
    r.y = w0 * a0.y + w1 * b0.y + w2 * c0.y + w3 * d0.y;
    r.z = w0 * a1.x + w1 * b1.x + w2 * c1.x + w3 * d1.x;
    r.w = w0 * a1.y + w1 * b1.y + w2 * c1.y + w3 * d1.y;
    *(float4*)(out + (size_t)bl * 1024 + coff) = r;
}

// ---------------- launch ----------------
extern "C" void kernel_launch(void* const* d_in, const int* in_sizes, int n_in,
                              void* d_out, int out_size)
{
    const float* X  = (const float*)d_in[0];
    const float* Kw = (const float*)d_in[1];
    const float* Kb = (const float*)d_in[2];
    const float* Vw = (const float*)d_in[3];
    const float* Vb = (const float*)d_in[4];
    const float* Bw = (const float*)d_in[5];
    const float* RH = (const float*)d_in[6];
    float* out = (float*)d_out;

    cudaFuncSetAttribute(gemm_f16, cudaFuncAttributeMaxDynamicSharedMemorySize, GEMM_SMEM);

    conv_x<<<(int)(((size_t)M_TOT * HIDN) / (256 * 8)), 256>>>(X);
    transpose_w<<<dim3(64, 32), dim3(32, 8)>>>(Kw, Vw);
    gemm_f16<<<dim3(8, 128), 256, GEMM_SMEM>>>(Kb, Vb, RH);
    fixup2<<<512, 256>>>(X, Kb, RH);
    scan_kernel<<<BSZ * NHD, 32>>>();
    gather_kernel<<<M_TOT * NHD / 16, 256>>>(Bw, out);
}

// round 16
// speedup vs baseline: 1.0716x; 1.0716x over previous
#include <cuda_runtime.h>
#include <cuda_fp16.h>
#include <cuda_bf16.h>
#include <stdint.h>

#define BSZ   8
#define LEN   2048
#define HIDN  1024
#define NHD   16
#define HDIM  64
#define M_TOT (BSZ * LEN)
#define FIX_TAU 4e-3f
#define FIX_CAP (M_TOT * NHD)

__device__ __half g_V1[(size_t)M_TOT * (NHD * HDIM)];
__device__ __half g_Xh[(size_t)M_TOT * HIDN];
__device__ __half g_WTh[(size_t)2048 * HIDN];   // [n][k] fp16 transposed weights
__device__ float  g_KTf[(size_t)1024 * HIDN];   // [n][k] fp32 transposed K weights
__device__ float  g_dots[M_TOT * NHD];
__device__ int2   g_fmap[M_TOT * NHD];
__device__ int2   g_bmap[M_TOT * NHD];
__device__ int    g_fix_cnt;
__device__ int    g_fix_ids[FIX_CAP];

// ---------------- helpers ----------------
__device__ __forceinline__ uint32_t smem_u32(const void* p) {
    return (uint32_t)__cvta_generic_to_shared(p);
}
__device__ __forceinline__ void cp_async16(uint32_t saddr, const void* gptr) {
    asm volatile("cp.async.ca.shared.global [%0], [%1], 16;\n" :: "r"(saddr), "l"(gptr));
}
__device__ __forceinline__ void cp_commit() { asm volatile("cp.async.commit_group;\n"); }
__device__ __forceinline__ void cp_wait1() { asm volatile("cp.async.wait_group 1;\n"); }

__device__ __forceinline__ void ldsm4(uint32_t* r, uint32_t addr) {
    asm volatile("ldmatrix.sync.aligned.m8n8.x4.shared.b16 {%0,%1,%2,%3}, [%4];"
        : "=r"(r[0]), "=r"(r[1]), "=r"(r[2]), "=r"(r[3]) : "r"(addr));
}
__device__ __forceinline__ void mma_f16(float* d, const uint32_t* a, const uint32_t* b) {
    asm volatile("mma.sync.aligned.m16n8k16.row.col.f32.f16.f16.f32 "
        "{%0,%1,%2,%3},{%4,%5,%6,%7},{%8,%9},{%0,%1,%2,%3};\n"
        : "+f"(d[0]), "+f"(d[1]), "+f"(d[2]), "+f"(d[3])
        : "r"(a[0]), "r"(a[1]), "r"(a[2]), "r"(a[3]), "r"(b[0]), "r"(b[1]));
}
// Neumaier compensated accumulate (branchless)
__device__ __forceinline__ void acc2(float& s, float& c, float v) {
    float t = s + v;
    float e1 = (s - t) + v;
    float e2 = (v - t) + s;
    c += (fabsf(s) >= fabsf(v)) ? e1 : e2;
    s = t;
}

// ---------------- pre-pass: X -> fp16 (+ counter init) ----------------
__global__ __launch_bounds__(256) void conv_x(const float* __restrict__ X)
{
    if (blockIdx.x == 0 && threadIdx.x == 0) g_fix_cnt = 0;
    size_t i = ((size_t)blockIdx.x * 256 + threadIdx.x) * 8;
    float4 v0 = *(const float4*)(X + i);
    float4 v1 = *(const float4*)(X + i + 4);
    __half2 h0 = __floats2half2_rn(v0.x, v0.y);
    __half2 h1 = __floats2half2_rn(v0.z, v0.w);
    __half2 h2 = __floats2half2_rn(v1.x, v1.y);
    __half2 h3 = __floats2half2_rn(v1.z, v1.w);
    uint4 o;
    o.x = *(uint32_t*)&h0; o.y = *(uint32_t*)&h1;
    o.z = *(uint32_t*)&h2; o.w = *(uint32_t*)&h3;
    *(uint4*)(g_Xh + i) = o;
}

// ---------------- pre-pass: W transpose -> fp16 [n][k] (+ fp32 for K half) ----
__global__ __launch_bounds__(256) void transpose_w(
    const float* __restrict__ Kw, const float* __restrict__ Vw)
{
    __shared__ float t[32][33];
    const int n0 = blockIdx.x * 32, k0 = blockIdx.y * 32;
    const float* W = (n0 < 1024) ? Kw : Vw;
    const int nb = n0 & 1023;
    const int tx = threadIdx.x, ty = threadIdx.y;
    #pragma unroll
    for (int r = ty; r < 32; r += 8)
        t[r][tx] = W[(size_t)(k0 + r) * 1024 + nb + tx];
    __syncthreads();
    #pragma unroll
    for (int r = ty; r < 32; r += 8) {
        float v = t[tx][r];
        g_WTh[(size_t)(n0 + r) * 1024 + k0 + tx] = __float2half_rn(v);
        if (n0 < 1024)
            g_KTf[(size_t)(n0 + r) * 1024 + k0 + tx] = v;
    }
}

// ---------------- fp16 mma GEMM (R13 shape): CTA 128x128x32, warp 32x64 -----
#define AROW 80
#define TILE_B (128 * AROW)
#define STG 3
#define GEMM_SMEM (2 * STG * TILE_B)   // 61440

__device__ __forceinline__ void load_tiles_f16(int m0, int n0, int kt, int st, uint32_t sb, int tid)
{
    const int kk = kt * 32;
    const uint32_t sA = sb + st * TILE_B;
    const uint32_t sB = sb + (STG + st) * TILE_B;
    #pragma unroll
    for (int i = 0; i < 2; i++) {
        int c = tid + i * 256, row = c >> 2, q = c & 3;
        cp_async16(sA + (uint32_t)(row * AROW + q * 16),
                   g_Xh + (size_t)(m0 + row) * 1024 + kk + q * 8);
    }
    #pragma unroll
    for (int i = 0; i < 2; i++) {
        int c = tid + i * 256, row = c >> 2, q = c & 3;
        cp_async16(sB + (uint32_t)(row * AROW + q * 16),
                   g_WTh + (size_t)(n0 + row) * 1024 + kk + q * 8);
    }
}

__global__ __launch_bounds__(256) void gemm_f16(
    const float* __restrict__ Kb, const float* __restrict__ Vb,
    const float* __restrict__ RH)
{
    extern __shared__ char smem[];
    const uint32_t sb = smem_u32(smem);
    const int tid = threadIdx.x, wid = tid >> 5, lane = tid & 31;
    const int wm = wid & 3, wn = wid >> 2;
    const int m0 = blockIdx.y * 128;
    const int j0 = blockIdx.x * 128;
    const int n0 = j0;

    float acc[2][8][4];
    #pragma unroll
    for (int a = 0; a < 2; a++)
        #pragma unroll
        for (int b = 0; b < 8; b++)
            #pragma unroll
            for (int c = 0; c < 4; c++) acc[a][b][c] = 0.f;

    load_tiles_f16(m0, n0, 0, 0, sb, tid); cp_commit();
    load_tiles_f16(m0, n0, 1, 1, sb, tid); cp_commit();

    const int j = lane >> 3, r = lane & 7;
    const int KT = 32;
    for (int kt = 0; kt < KT; kt++) {
        cp_wait1();
        __syncthreads();
        if (kt + 2 < KT) load_tiles_f16(m0, n0, kt + 2, (kt + 2) % STG, sb, tid);
        cp_commit();

        const int st = kt % STG;
        const uint32_t sA = sb + st * TILE_B;
        const uint32_t sB = sb + (STG + st) * TILE_B;
        #pragma unroll
        for (int kh = 0; kh < 2; kh++) {
            uint32_t a0[4], a1[4];
            const uint32_t arow = (uint32_t)(wm * 32 + ((j & 1) << 3) + r);
            const uint32_t acol = (uint32_t)((kh << 4) + ((j >> 1) << 3));
            ldsm4(a0, sA + arow * AROW + acol * 2);
            ldsm4(a1, sA + (arow + 16) * AROW + acol * 2);
            #pragma unroll
            for (int g2 = 0; g2 < 4; g2++) {
                uint32_t bm[4];
                const uint32_t brow = (uint32_t)(wn * 64 + (g2 << 4) + ((j >> 1) << 3) + r);
                const uint32_t bcol = (uint32_t)((kh << 4) + ((j & 1) << 3));
                ldsm4(bm, sB + brow * AROW + bcol * 2);
                mma_f16(acc[0][2 * g2],     a0, &bm[0]);
                mma_f16(acc[1][2 * g2],     a1, &bm[0]);
                mma_f16(acc[0][2 * g2 + 1], a0, &bm[2]);
                mma_f16(acc[1][2 * g2 + 1], a1, &bm[2]);
            }
        }
    }

    const int g = lane >> 2, tg = lane & 3;
    if (j0 < 1024) {
        const int head = (j0 >> 6) + wn;
        const float* rh = RH + head * HDIM;
        float dotp[4] = {0.f, 0.f, 0.f, 0.f};
        #pragma unroll
        for (int mt = 0; mt < 2; mt++) {
            #pragma unroll
            for (int nt = 0; nt < 8; nt++) {
                int ch = nt * 8 + 2 * tg;
                int jc = j0 + wn * 64 + ch;
                float b0 = Kb[jc], b1 = Kb[jc + 1];
                float w0 = rh[ch], w1 = rh[ch + 1];
                float v;
                v = fmaxf(acc[mt][nt][0] + b0, 0.f); dotp[mt * 2 + 0] += v * w0;
                v = fmaxf(acc[mt][nt][1] + b1, 0.f); dotp[mt * 2 + 0] += v * w1;
                v = fmaxf(acc[mt][nt][2] + b0, 0.f); dotp[mt * 2 + 1] += v * w0;
                v = fmaxf(acc[mt][nt][3] + b1, 0.f); dotp[mt * 2 + 1] += v * w1;
            }
        }
        #pragma unroll
        for (int i = 0; i < 4; i++) {
            dotp[i] += __shfl_xor_sync(0xffffffffu, dotp[i], 1);
            dotp[i] += __shfl_xor_sync(0xffffffffu, dotp[i], 2);
        }
        if (tg == 0) {
            #pragma unroll
            for (int mt = 0; mt < 2; mt++) {
                int rr = m0 + wm * 32 + mt * 16 + g;
                float d0 = dotp[mt * 2 + 0], d1 = dotp[mt * 2 + 1];
                int id0 = rr * NHD + head, id1 = (rr + 8) * NHD + head;
                g_dots[id0] = d0;
                g_dots[id1] = d1;
                if (fabsf(d0 - 0.5f) < FIX_TAU) g_fix_ids[atomicAdd(&g_fix_cnt, 1)] = id0;
                if (fabsf(d1 - 0.5f) < FIX_TAU) g_fix_ids[atomicAdd(&g_fix_cnt, 1)] = id1;
            }
        }
    } else {
        #pragma unroll
        for (int mt = 0; mt < 2; mt++) {
            #pragma unroll
            for (int nt = 0; nt < 8; nt++) {
                int jv = (j0 - 1024) + wn * 64 + nt * 8 + 2 * tg;
                float b0 = Vb[jv], b1 = Vb[jv + 1];
                int rr = m0 + wm * 32 + mt * 16 + g;
                __half2 h0 = __floats2half2_rn(fmaxf(acc[mt][nt][0] + b0, 0.f),
                                               fmaxf(acc[mt][nt][1] + b1, 0.f));
                __half2 h1 = __floats2half2_rn(fmaxf(acc[mt][nt][2] + b0, 0.f),
                                               fmaxf(acc[mt][nt][3] + b1, 0.f));
                *(__half2*)&g_V1[(size_t)rr * 1024 + jv] = h0;
                *(__half2*)&g_V1[(size_t)(rr + 8) * 1024 + jv] = h1;
            }
        }
    }
}

// ------------- compensated-fp32 fixup, 8-row ILP per warp -------------------
// Each warp processes its 8 head-channels CONCURRENTLY (8 independent (s,c)
// chains); one shared X load per k per lane feeds all 8 rows.
__global__ __launch_bounds__(256) void fixup3(
    const float* __restrict__ X, const float* __restrict__ Kb,
    const float* __restrict__ RH)
{
    __shared__ float s_s[8], s_c[8];
    const int tid = threadIdx.x, wid = tid >> 5, lane = tid & 31;
    int cnt = g_fix_cnt;
    if (cnt > FIX_CAP) cnt = FIX_CAP;

    for (int i = blockIdx.x; i < cnt; i += gridDim.x) {
        const int t = g_fix_ids[i];
        const int m = t >> 4, n = t & 15;
        const float* xr = X + ((size_t)m << 10);
        const float* wbase = g_KTf + ((size_t)(n * 64 + wid * 8) << 10);

        float s[8], c[8];
        #pragma unroll
        for (int rr = 0; rr < 8; rr++) { s[rr] = 0.f; c[rr] = 0.f; }

        for (int it = 0; it < 32; it++) {
            const int k = it * 32 + lane;
            const float a = xr[k];
            #pragma unroll
            for (int rr = 0; rr < 8; rr++) {
                float w = wbase[((size_t)rr << 10) + k];
                float p = a * w;
                float e = fmaf(a, w, -p);
                acc2(s[rr], c[rr], p);
                c[rr] += e;
            }
        }
        // reduce each row's (s,c) across the warp
        #pragma unroll
        for (int rr = 0; rr < 8; rr++) {
            #pragma unroll
            for (int off = 16; off > 0; off >>= 1) {
                float s2 = __shfl_down_sync(0xffffffffu, s[rr], off);
                float c2 = __shfl_down_sync(0xffffffffu, c[rr], off);
                acc2(s[rr], c[rr], s2);
                c[rr] += c2;
            }
        }
        if (lane == 0) {
            float ws = 0.f, wc = 0.f;
            #pragma unroll
            for (int rr = 0; rr < 8; rr++) {
                const int h = wid * 8 + rr;
                float pre = s[rr] + c[rr] + Kb[n * 64 + h];
                float rv = fmaxf(pre, 0.f) * RH[n * 64 + h];
                acc2(ws, wc, rv);
            }
            s_s[wid] = ws; s_c[wid] = wc;
        }
        __syncthreads();
        if (tid == 0) {
            float ss = 0.f, cc = 0.f;
            #pragma unroll
            for (int w2 = 0; w2 < 8; w2++) { acc2(ss, cc, s_s[w2]); cc += s_c[w2]; }
            g_dots[t] = ss + cc;
        }
        __syncthreads();
    }
}

// ---------------- warp-segmented nearest-valid scan ----------------
struct Seg { int cnt, v1, v2; };

__device__ __forceinline__ Seg seg_combine(const Seg& prev, const Seg& cur) {
    Seg r;
    if (cur.cnt >= 2) r = cur;
    else if (cur.cnt == 1) { r.cnt = min(prev.cnt + 1, 2); r.v1 = cur.v1; r.v2 = prev.v1; }
    else r = prev;
    return r;
}

__global__ void scan_kernel()
{
    const int bidx = blockIdx.x >> 4;
    const int n = blockIdx.x & 15;
    const int lane = threadIdx.x;
    const int base_l = lane * 64;

    const float* dp = g_dots + ((size_t)bidx * LEN) * NHD + n;
    unsigned long long bits = 0ull;
    for (int j = 0; j < 64; j++)
        if (__ldg(&dp[(size_t)(base_l + j) * NHD]) > 0.5f) bits |= (1ull << j);

    { // forward: ignore pos 0, defaults 0
        unsigned long long fb = bits;
        if (lane == 0) fb &= ~1ull;
        Seg s; s.cnt = 0; s.v1 = 0; s.v2 = 0;
        for (int j = 0; j < 64; j++)
            if ((fb >> j) & 1ull) { s.v2 = s.v1; s.v1 = base_l + j; s.cnt = min(s.cnt + 1, 2); }
        Seg inc = s;
        for (int d = 1; d < 32; d <<= 1) {
            Seg o;
            o.cnt = __shfl_up_sync(0xffffffffu, inc.cnt, d);
            o.v1  = __shfl_up_sync(0xffffffffu, inc.v1, d);
            o.v2  = __shfl_up_sync(0xffffffffu, inc.v2, d);
            if (lane >= d) inc = seg_combine(o, inc);
        }
        Seg ex;
        ex.cnt = __shfl_up_sync(0xffffffffu, inc.cnt, 1);
        ex.v1  = __shfl_up_sync(0xffffffffu, inc.v1, 1);
        ex.v2  = __shfl_up_sync(0xffffffffu, inc.v2, 1);
        if (lane == 0) { ex.cnt = 0; ex.v1 = 0; ex.v2 = 0; }
        int a = (ex.cnt >= 1) ? ex.v1 : 0;
        int b = (ex.cnt >= 2) ? ex.v2 : 0;
        int2* out = g_fmap + ((size_t)bidx * LEN) * NHD + n;
        for (int j = 0; j < 64; j++) {
            int p = base_l + j;
            if ((fb >> j) & 1ull) { b = a; a = p; }
            out[(size_t)p * NHD] = make_int2(a, b);
        }
    }

    { // backward: ignore pos L-1, store mirrored index, defaults L-1
        unsigned long long bb = bits;
        if (lane == 31) bb &= ~(1ull << 63);
        Seg s; s.cnt = 0; s.v1 = LEN - 1; s.v2 = LEN - 1;
        for (int j = 63; j >= 0; j--)
            if ((bb >> j) & 1ull) { s.v2 = s.v1; s.v1 = (LEN - 1) - (base_l + j); s.cnt = min(s.cnt + 1, 2); }
        Seg inc = s;
        for (int d = 1; d < 32; d <<= 1) {
            Seg o;
            o.cnt = __shfl_down_sync(0xffffffffu, inc.cnt, d);
            o.v1  = __shfl_down_sync(0xffffffffu, inc.v1, d);
            o.v2  = __shfl_down_sync(0xffffffffu, inc.v2, d);
            if (lane + d < 32) inc = seg_combine(o, inc);
        }
        Seg ex;
        ex.cnt = __shfl_down_sync(0xffffffffu, inc.cnt, 1);
        ex.v1  = __shfl_down_sync(0xffffffffu, inc.v1, 1);
        ex.v2  = __shfl_down_sync(0xffffffffu, inc.v2, 1);
        if (lane == 31) { ex.cnt = 0; ex.v1 = LEN - 1; ex.v2 = LEN - 1; }
        int a = (ex.cnt >= 1) ? ex.v1 : (LEN - 1);
        int b = (ex.cnt >= 2) ? ex.v2 : (LEN - 1);
        int2* out = g_bmap + ((size_t)bidx * LEN) * NHD + n;
        for (int j = 63; j >= 0; j--) {
            int p = base_l + j;
            if ((bb >> j) & 1ull) { b = a; a = (LEN - 1) - p; }
            out[(size_t)p * NHD] = make_int2(a, b);
        }
    }
}

// ---------------- weighted gather (fp16 V1) ----------------
__global__ __launch_bounds__(256) void gather_kernel(
    const float* __restrict__ Bw, float* __restrict__ out)
{
    int gid = blockIdx.x * 16 + (threadIdx.x >> 4);
    int q = threadIdx.x & 15;
    int n = gid & 15;
    int bl = gid >> 4;
    int b = bl >> 11;
    int2 fm = g_fmap[(size_t)bl * NHD + n];
    int2 bm = g_bmap[(size_t)bl * NHD + n];
    const __half* vbase = g_V1 + (((size_t)b << 11) << 10);
    size_t coff = (size_t)n * 64 + q * 4;
    uint2 u0 = *(const uint2*)(vbase + ((size_t)fm.x << 10) + coff);
    uint2 u1 = *(const uint2*)(vbase + ((size_t)fm.y << 10) + coff);
    uint2 u2 = *(const uint2*)(vbase + ((size_t)bm.x << 10) + coff);
    uint2 u3 = *(const uint2*)(vbase + ((size_t)bm.y << 10) + coff);
    float w0 = Bw[n * 4 + 0], w1 = Bw[n * 4 + 1], w2 = Bw[n * 4 + 2], w3 = Bw[n * 4 + 3];
    float2 a0 = __half22float2(*(__half2*)&u0.x), a1 = __half22float2(*(__half2*)&u0.y);
    float2 b0 = __half22float2(*(__half2*)&u1.x), b1 = __half22float2(*(__half2*)&u1.y);
    float2 c0 = __half22float2(*(__half2*)&u2.x), c1 = __half22float2(*(__half2*)&u2.y);
    float2 d0 = __half22float2(*(__half2*)&u3.x), d1 = __half22float2(*(__half2*)&u3.y);
    float4 r;
    r.x = w0 * a0.x + w1 * b0.x + w2 * c0.x + w3 * d0.x;
    r.y = w0 * a0.y + w1 * b0.y + w2 * c0.y + w3 * d0.y;
    r.z = w0 * a1.x + w1 * b1.x + w2 * c1.x + w3 * d1.x;
    r.w = w0 * a1.y + w1 * b1.y + w2 * c1.y + w3 * d1.y;
    *(float4*)(out + (size_t)bl * 1024 + coff) = r;
}

// ---------------- launch ----------------
extern "C" void kernel_launch(void* const* d_in, const int* in_sizes, int n_in,
                              void* d_out, int out_size)
{
    const float* X  = (const float*)d_in[0];
    const float* Kw = (const float*)d_in[1];
    const float* Kb = (const float*)d_in[2];
    const float* Vw = (const float*)d_in[3];
    const float* Vb = (const float*)d_in[4];
    const float* Bw = (const float*)d_in[5];
    const float* RH = (const float*)d_in[6];
    float* out = (float*)d_out;

    cudaFuncSetAttribute(gemm_f16, cudaFuncAttributeMaxDynamicSharedMemorySize, GEMM_SMEM);

    conv_x<<<(int)(((size_t)M_TOT * HIDN) / (256 * 8)), 256>>>(X);
    transpose_w<<<dim3(64, 32), dim3(32, 8)>>>(Kw, Vw);
    gemm_f16<<<dim3(16, 128), 256, GEMM_SMEM>>>(Kb, Vb, RH);
    fixup3<<<1024, 256>>>(X, Kb, RH);
    scan_kernel<<<BSZ * NHD, 32>>>();
    gather_kernel<<<M_TOT * NHD / 16, 256>>>(Bw, out);
}